// round 1
// baseline (speedup 1.0000x reference)
#include <cuda_runtime.h>
#include <cuda_bf16.h>
#include <math.h>

#define BATCH   16384
#define FDIM    64
#define CTXD    128
#define HID     512
#define NLAYERS 8
#define NBLK    2
#define KIN     160   // 32 id cols + 128 context cols

// ---------------- scratch (device globals; no allocs allowed) ----------------
__device__ float         g_x[2][BATCH * FDIM];
__device__ float         g_logdet[BATCH];
__device__ __nv_bfloat16 g_Ain[BATCH * KIN];
__device__ __nv_bfloat16 g_h[2][BATCH * HID];
__device__ __nv_bfloat16 g_Win[NLAYERS * KIN * HID];
__device__ __nv_bfloat16 g_Wh[NLAYERS * NBLK * HID * HID];
__device__ __nv_bfloat16 g_Wout[NLAYERS * HID * FDIM];

// ---------------- PTX helpers ----------------
__device__ __forceinline__ unsigned smem_u32(const void* p) {
    return (unsigned)__cvta_generic_to_shared(p);
}
__device__ __forceinline__ void cp16(void* s, const void* g) {
    asm volatile("cp.async.cg.shared.global [%0], [%1], 16;\n"
                 :: "r"(smem_u32(s)), "l"(g));
}
__device__ __forceinline__ void cp_commit() { asm volatile("cp.async.commit_group;\n" ::); }
__device__ __forceinline__ void cp_wait0()  { asm volatile("cp.async.wait_group 0;\n" ::); }

__device__ __forceinline__ void ldmA(unsigned* r, const void* p) {
    asm volatile("ldmatrix.sync.aligned.m8n8.x4.shared.b16 {%0,%1,%2,%3}, [%4];\n"
                 : "=r"(r[0]), "=r"(r[1]), "=r"(r[2]), "=r"(r[3])
                 : "r"(smem_u32(p)));
}
__device__ __forceinline__ void ldmBT(unsigned* r, const void* p) {
    asm volatile("ldmatrix.sync.aligned.m8n8.x4.trans.shared.b16 {%0,%1,%2,%3}, [%4];\n"
                 : "=r"(r[0]), "=r"(r[1]), "=r"(r[2]), "=r"(r[3])
                 : "r"(smem_u32(p)));
}
__device__ __forceinline__ void mma16816(float* d, const unsigned* a, unsigned b0, unsigned b1) {
    asm volatile("mma.sync.aligned.m16n8k16.row.col.f32.bf16.bf16.f32 "
                 "{%0,%1,%2,%3}, {%4,%5,%6,%7}, {%8,%9}, {%0,%1,%2,%3};\n"
                 : "+f"(d[0]), "+f"(d[1]), "+f"(d[2]), "+f"(d[3])
                 : "r"(a[0]), "r"(a[1]), "r"(a[2]), "r"(a[3]), "r"(b0), "r"(b1));
}

// Strides (in bf16 elems); both give 16B-aligned, conflict-free ldmatrix rows.
#define AS_STRIDE 40   // 128 rows x 32 cols + pad  (row = 80B, 5x16B)
#define BS_STRIDE 80   // 32 rows x 64 cols + pad   (row = 160B, 10x16B)
#define AS_BUF (128 * AS_STRIDE)
#define BS_BUF (32 * BS_STRIDE)

// ---------------- shared GEMM mainloop: C_tile(128x64) = A(MxK) @ W(KxN) ----------------
// 256 threads, 8 warps in 4(M) x 2(N) arrangement; warp tile 32x32.
__device__ __forceinline__ void gemm_mainloop(
    const __nv_bfloat16* A, const __nv_bfloat16* W, int K, int N,
    int bm0, int bn0, __nv_bfloat16* As, __nv_bfloat16* Bs,
    float acc[2][4][4])
{
    const int tid  = threadIdx.x;
    const int lane = tid & 31;
    const int warp = tid >> 5;
    const int wm   = warp & 3;
    const int wn   = warp >> 2;

    const int KT = K >> 5;  // BK = 32

    auto load_tile = [&](int kt, int buf) {
        const __nv_bfloat16* Ag = A + (long)bm0 * K + kt * 32;
        #pragma unroll
        for (int it = 0; it < 2; ++it) {
            int c   = tid + it * 256;
            int row = c >> 2;
            int co  = (c & 3) * 8;
            cp16(As + buf * AS_BUF + row * AS_STRIDE + co, Ag + (long)row * K + co);
        }
        {
            int row = tid >> 3;
            int co  = (tid & 7) * 8;
            cp16(Bs + buf * BS_BUF + row * BS_STRIDE + co,
                 W + (long)(kt * 32 + row) * N + bn0 + co);
        }
    };

    load_tile(0, 0);
    cp_commit();

    for (int kt = 0; kt < KT; ++kt) {
        cp_wait0();
        __syncthreads();
        if (kt + 1 < KT) load_tile(kt + 1, (kt + 1) & 1);
        cp_commit();

        const __nv_bfloat16* as = As + (kt & 1) * AS_BUF;
        const __nv_bfloat16* bs = Bs + (kt & 1) * BS_BUF;

        #pragma unroll
        for (int ks = 0; ks < 2; ++ks) {
            unsigned a[2][4], bq[2][4];
            int ar = wm * 32 + (lane & 15);
            int ac = ks * 16 + (lane >> 4) * 8;
            ldmA(a[0], as + ar * AS_STRIDE + ac);
            ldmA(a[1], as + (ar + 16) * AS_STRIDE + ac);
            int br = ks * 16 + (lane & 15);
            ldmBT(bq[0], bs + br * BS_STRIDE + wn * 32 + 0  + (lane >> 4) * 8);
            ldmBT(bq[1], bs + br * BS_STRIDE + wn * 32 + 16 + (lane >> 4) * 8);
            #pragma unroll
            for (int m = 0; m < 2; ++m)
                #pragma unroll
                for (int nb = 0; nb < 2; ++nb) {
                    mma16816(acc[m][nb * 2 + 0], a[m], bq[nb][0], bq[nb][1]);
                    mma16816(acc[m][nb * 2 + 1], a[m], bq[nb][2], bq[nb][3]);
                }
        }
    }
}

// ---------------- GEMM + bias + relu -> bf16 h buffer ----------------
__global__ void __launch_bounds__(256)
gemm_relu_kernel(int asel, int csel, int wsel, long woff,
                 const float* __restrict__ bias, int K, int N)
{
    __shared__ __align__(16) __nv_bfloat16 As[2 * AS_BUF];
    __shared__ __align__(16) __nv_bfloat16 Bs[2 * BS_BUF];

    const __nv_bfloat16* A = (asel == 0) ? g_Ain : g_h[asel - 1];
    const __nv_bfloat16* W = ((wsel == 0) ? g_Win : g_Wh) + woff;
    __nv_bfloat16* C = g_h[csel];

    int bm0 = blockIdx.x * 128;
    int bn0 = blockIdx.y * 64;

    float acc[2][4][4] = {};
    gemm_mainloop(A, W, K, N, bm0, bn0, As, Bs, acc);

    const int lane = threadIdx.x & 31;
    const int warp = threadIdx.x >> 5;
    const int wm = warp & 3, wn = warp >> 2;

    #pragma unroll
    for (int m = 0; m < 2; ++m)
        #pragma unroll
        for (int nt = 0; nt < 4; ++nt) {
            int gr = bm0 + wm * 32 + m * 16 + (lane >> 2);
            int gc = bn0 + wn * 32 + nt * 8 + (lane & 3) * 2;
            float b0 = bias[gc], b1 = bias[gc + 1];
            float v0 = fmaxf(acc[m][nt][0] + b0, 0.f);
            float v1 = fmaxf(acc[m][nt][1] + b1, 0.f);
            float v2 = fmaxf(acc[m][nt][2] + b0, 0.f);
            float v3 = fmaxf(acc[m][nt][3] + b1, 0.f);
            __nv_bfloat162 p0, p1;
            p0.x = __float2bfloat16(v0); p0.y = __float2bfloat16(v1);
            p1.x = __float2bfloat16(v2); p1.y = __float2bfloat16(v3);
            *reinterpret_cast<__nv_bfloat162*>(C + (long)gr * N + gc) = p0;
            *reinterpret_cast<__nv_bfloat162*>(C + (long)(gr + 8) * N + gc) = p1;
        }
}

// ---------------- final GEMM of a layer + flow epilogue ----------------
#define PS_STRIDE 65
__global__ void __launch_bounds__(256)
gemm_out_kernel(int hsel, long woff, const float* __restrict__ bias,
                int layer, const int* __restrict__ perm, float* __restrict__ d_out)
{
    // union: GEMM staging (As 20480B + Bs 10240B) vs p-buffer (128*65*4 = 33280B)
    __shared__ __align__(16) char smraw[128 * PS_STRIDE * 4];
    __shared__ int sperm[64];
    __nv_bfloat16* As = (__nv_bfloat16*)smraw;
    __nv_bfloat16* Bs = (__nv_bfloat16*)(smraw + 2 * AS_BUF * 2);
    float* ps = (float*)smraw;

    if (perm && threadIdx.x < 64) sperm[threadIdx.x] = perm[threadIdx.x];

    const __nv_bfloat16* A = g_h[hsel];
    const __nv_bfloat16* W = g_Wout + woff;
    int bm0 = blockIdx.x * 128;

    float acc[2][4][4] = {};
    gemm_mainloop(A, W, HID, FDIM, bm0, 0, As, Bs, acc);
    __syncthreads();  // everyone done with As/Bs before ps overwrites them

    const int lane = threadIdx.x & 31;
    const int warp = threadIdx.x >> 5;
    const int wm = warp & 3, wn = warp >> 2;

    #pragma unroll
    for (int m = 0; m < 2; ++m)
        #pragma unroll
        for (int nt = 0; nt < 4; ++nt) {
            int r = wm * 32 + m * 16 + (lane >> 2);
            int c = wn * 32 + nt * 8 + (lane & 3) * 2;
            float b0 = bias[c], b1 = bias[c + 1];
            ps[r * PS_STRIDE + c]             = acc[m][nt][0] + b0;
            ps[r * PS_STRIDE + c + 1]         = acc[m][nt][1] + b1;
            ps[(r + 8) * PS_STRIDE + c]       = acc[m][nt][2] + b0;
            ps[(r + 8) * PS_STRIDE + c + 1]   = acc[m][nt][3] + b1;
        }
    __syncthreads();

    if (threadIdx.x < 128) {
        int  r  = threadIdx.x;
        long gr = bm0 + r;
        const float* xc = g_x[layer & 1] + gr * FDIM;
        float* prow = ps + r * PS_STRIDE;
        const int toff = layer & 1;  // layer even -> transform even cols

        float scale[32], shift[32];
        float ld = 0.f;
        #pragma unroll
        for (int k = 0; k < 32; ++k) {
            shift[k] = prow[k];
            float s  = prow[32 + k];
            scale[k] = 1.f / (1.f + expf(-(s + 2.f))) + 0.001f;
            ld += logf(scale[k]);
        }
        // build x_new in natural column order (overwrite prow)
        #pragma unroll
        for (int k = 0; k < 32; ++k) {
            int t  = 2 * k + toff;
            int id = 2 * k + 1 - toff;
            float xt = xc[t] * scale[k] + shift[k];
            float xi = xc[id];
            prow[t]  = xt;
            prow[id] = xi;
        }

        if (perm) {
            g_logdet[gr] += ld;
            float* xn = g_x[(layer & 1) ^ 1] + gr * FDIM;
            const int idoff = layer & 1;  // next layer's identity-col offset
            #pragma unroll
            for (int j = 0; j < 64; ++j) xn[j] = prow[sperm[j]];
            #pragma unroll
            for (int k = 0; k < 32; ++k)
                g_Ain[gr * KIN + k] = __float2bfloat16(prow[sperm[2 * k + idoff]]);
        } else {
            float tot = g_logdet[gr] + ld;
            #pragma unroll
            for (int j = 0; j < 64; ++j) {
                float v = prow[j];
                v = fminf(fmaxf(v, -1.f), 1.f);
                d_out[gr * FDIM + j] = v;
            }
            d_out[(long)BATCH * FDIM + gr] = tot;
        }
    }
}

// ---------------- init: x0 = clip(inputs), build A_in(layer0), zero logdet ----------------
__global__ void init_kernel(const float* __restrict__ inputs,
                            const float* __restrict__ context)
{
    int r = blockIdx.x * 4 + threadIdx.y;
    int c = threadIdx.x;  // 0..63
    __shared__ float xs[4][64];

    float v = inputs[(long)r * FDIM + c];
    v = fminf(fmaxf(v, -1.f), 1.f);
    g_x[0][(long)r * FDIM + c] = v;
    xs[threadIdx.y][c] = v;

    g_Ain[(long)r * KIN + 32 + c]      = __float2bfloat16(context[(long)r * CTXD + c]);
    g_Ain[(long)r * KIN + 32 + 64 + c] = __float2bfloat16(context[(long)r * CTXD + 64 + c]);
    __syncthreads();
    if (c < 32)  // layer 0: identity = odd columns
        g_Ain[(long)r * KIN + c] = __float2bfloat16(xs[threadIdx.y][2 * c + 1]);
    if (c == 0) g_logdet[r] = 0.f;
}

// ---------------- weight fp32 -> bf16 ----------------
__global__ void cvt_kernel(const float* __restrict__ win,
                           const float* __restrict__ wh,
                           const float* __restrict__ wout)
{
    const long n1 = (long)NLAYERS * KIN * HID;
    const long n2 = (long)NLAYERS * NBLK * HID * HID;
    const long n3 = (long)NLAYERS * HID * FDIM;
    const long total = n1 + n2 + n3;
    for (long i = (long)blockIdx.x * blockDim.x + threadIdx.x; i < total;
         i += (long)gridDim.x * blockDim.x) {
        if (i < n1)            g_Win[i]           = __float2bfloat16(win[i]);
        else if (i < n1 + n2)  g_Wh[i - n1]       = __float2bfloat16(wh[i - n1]);
        else                   g_Wout[i - n1 - n2]= __float2bfloat16(wout[i - n1 - n2]);
    }
}

// ---------------- launch ----------------
extern "C" void kernel_launch(void* const* d_in, const int* in_sizes, int n_in,
                              void* d_out, int out_size)
{
    const float* inputs  = (const float*)d_in[0];
    const float* context = (const float*)d_in[1];
    const float* W_in    = (const float*)d_in[2];
    const float* b_in    = (const float*)d_in[3];
    const float* W_h     = (const float*)d_in[4];
    const float* b_h     = (const float*)d_in[5];
    const float* W_out   = (const float*)d_in[6];
    const float* b_out   = (const float*)d_in[7];
    const int*   perms   = (const int*)d_in[8];
    float* out = (float*)d_out;

    cvt_kernel<<<2048, 256>>>(W_in, W_h, W_out);
    init_kernel<<<BATCH / 4, dim3(64, 4)>>>(inputs, context);

    for (int i = 0; i < NLAYERS; ++i) {
        // h0 = relu([id, ctx] @ W_in[i] + b_in[i])
        gemm_relu_kernel<<<dim3(BATCH / 128, HID / 64), 256>>>(
            0, 0, 0, (long)i * KIN * HID, b_in + i * HID, KIN, HID);
        // h1 = relu(h0 @ W_h[i,0] + b)
        gemm_relu_kernel<<<dim3(BATCH / 128, HID / 64), 256>>>(
            1, 1, 1, (long)(i * NBLK + 0) * HID * HID, b_h + (i * NBLK + 0) * HID, HID, HID);
        // h0 = relu(h1 @ W_h[i,1] + b)
        gemm_relu_kernel<<<dim3(BATCH / 128, HID / 64), 256>>>(
            2, 0, 1, (long)(i * NBLK + 1) * HID * HID, b_h + (i * NBLK + 1) * HID, HID, HID);
        // p = h0 @ W_out[i] + b_out[i]; flow epilogue + permutation (+final output)
        const int* p = (i < NLAYERS - 1) ? (perms + i * FDIM) : (const int*)nullptr;
        gemm_out_kernel<<<BATCH / 128, 256>>>(
            0, (long)i * HID * FDIM, b_out + i * FDIM, i, p, out);
    }
}

// round 2
// speedup vs baseline: 1.0077x; 1.0077x over previous
#include <cuda_runtime.h>
#include <cuda_bf16.h>
#include <math.h>

#define BATCH   16384
#define FDIM    64
#define CTXD    128
#define HID     512
#define NLAYERS 8
#define NBLK    2
#define KIN     160   // 32 id cols + 128 context cols

// ---------------- scratch (device globals; no allocs allowed) ----------------
__device__ float         g_x[2][BATCH * FDIM];
__device__ float         g_logdet[BATCH];
__device__ __nv_bfloat16 g_Ain[BATCH * KIN];
__device__ __nv_bfloat16 g_h[2][BATCH * HID];
__device__ __nv_bfloat16 g_Win[NLAYERS * KIN * HID];
__device__ __nv_bfloat16 g_Wh[NLAYERS * NBLK * HID * HID];
__device__ __nv_bfloat16 g_Wout[NLAYERS * HID * FDIM];

// ---------------- PTX helpers ----------------
__device__ __forceinline__ unsigned smem_u32(const void* p) {
    return (unsigned)__cvta_generic_to_shared(p);
}
__device__ __forceinline__ void cp16(void* s, const void* g) {
    asm volatile("cp.async.cg.shared.global [%0], [%1], 16;\n"
                 :: "r"(smem_u32(s)), "l"(g));
}
__device__ __forceinline__ void cp_commit() { asm volatile("cp.async.commit_group;\n" ::); }
__device__ __forceinline__ void cp_wait0()  { asm volatile("cp.async.wait_group 0;\n" ::); }

__device__ __forceinline__ void ldmA(unsigned* r, const void* p) {
    asm volatile("ldmatrix.sync.aligned.m8n8.x4.shared.b16 {%0,%1,%2,%3}, [%4];\n"
                 : "=r"(r[0]), "=r"(r[1]), "=r"(r[2]), "=r"(r[3])
                 : "r"(smem_u32(p)));
}
__device__ __forceinline__ void ldmBT(unsigned* r, const void* p) {
    asm volatile("ldmatrix.sync.aligned.m8n8.x4.trans.shared.b16 {%0,%1,%2,%3}, [%4];\n"
                 : "=r"(r[0]), "=r"(r[1]), "=r"(r[2]), "=r"(r[3])
                 : "r"(smem_u32(p)));
}
__device__ __forceinline__ void mma16816(float* d, const unsigned* a, unsigned b0, unsigned b1) {
    asm volatile("mma.sync.aligned.m16n8k16.row.col.f32.bf16.bf16.f32 "
                 "{%0,%1,%2,%3}, {%4,%5,%6,%7}, {%8,%9}, {%0,%1,%2,%3};\n"
                 : "+f"(d[0]), "+f"(d[1]), "+f"(d[2]), "+f"(d[3])
                 : "r"(a[0]), "r"(a[1]), "r"(a[2]), "r"(a[3]), "r"(b0), "r"(b1));
}

// Strides (in bf16 elems); both give 16B-aligned, conflict-free ldmatrix rows.
#define AS_STRIDE 40   // 128 rows x 32 cols + pad  (row = 80B, 5x16B)
#define BS_STRIDE 80   // 32 rows x 64 cols + pad   (row = 160B, 10x16B)
#define AS_BUF (128 * AS_STRIDE)
#define BS_BUF (32 * BS_STRIDE)

// ---------------- shared GEMM mainloop: C_tile(128x64) = A(MxK) @ W(KxN) ----------------
// 256 threads, 8 warps in 4(M) x 2(N) arrangement; warp tile 32x32.
__device__ __forceinline__ void gemm_mainloop(
    const __nv_bfloat16* A, const __nv_bfloat16* W, int K, int N,
    int bm0, int bn0, __nv_bfloat16* As, __nv_bfloat16* Bs,
    float acc[2][4][4])
{
    const int tid  = threadIdx.x;
    const int lane = tid & 31;
    const int warp = tid >> 5;
    const int wm   = warp & 3;
    const int wn   = warp >> 2;

    const int KT = K >> 5;  // BK = 32

    auto load_tile = [&](int kt, int buf) {
        const __nv_bfloat16* Ag = A + (long)bm0 * K + kt * 32;
        #pragma unroll
        for (int it = 0; it < 2; ++it) {
            int c   = tid + it * 256;
            int row = c >> 2;
            int co  = (c & 3) * 8;
            cp16(As + buf * AS_BUF + row * AS_STRIDE + co, Ag + (long)row * K + co);
        }
        {
            int row = tid >> 3;
            int co  = (tid & 7) * 8;
            cp16(Bs + buf * BS_BUF + row * BS_STRIDE + co,
                 W + (long)(kt * 32 + row) * N + bn0 + co);
        }
    };

    load_tile(0, 0);
    cp_commit();

    for (int kt = 0; kt < KT; ++kt) {
        cp_wait0();
        __syncthreads();
        if (kt + 1 < KT) load_tile(kt + 1, (kt + 1) & 1);
        cp_commit();

        const __nv_bfloat16* as = As + (kt & 1) * AS_BUF;
        const __nv_bfloat16* bs = Bs + (kt & 1) * BS_BUF;

        #pragma unroll
        for (int ks = 0; ks < 2; ++ks) {
            unsigned a[2][4], bq[2][4];
            int ar = wm * 32 + (lane & 15);
            int ac = ks * 16 + (lane >> 4) * 8;
            ldmA(a[0], as + ar * AS_STRIDE + ac);
            ldmA(a[1], as + (ar + 16) * AS_STRIDE + ac);
            int br = ks * 16 + (lane & 15);
            ldmBT(bq[0], bs + br * BS_STRIDE + wn * 32 + 0  + (lane >> 4) * 8);
            ldmBT(bq[1], bs + br * BS_STRIDE + wn * 32 + 16 + (lane >> 4) * 8);
            #pragma unroll
            for (int m = 0; m < 2; ++m)
                #pragma unroll
                for (int nb = 0; nb < 2; ++nb) {
                    mma16816(acc[m][nb * 2 + 0], a[m], bq[nb][0], bq[nb][1]);
                    mma16816(acc[m][nb * 2 + 1], a[m], bq[nb][2], bq[nb][3]);
                }
        }
    }
}

// ---------------- GEMM + bias + relu -> bf16 h buffer ----------------
__global__ void __launch_bounds__(256)
gemm_relu_kernel(int asel, int csel, int wsel, long woff,
                 const float* __restrict__ bias, int K, int N)
{
    __shared__ __align__(16) __nv_bfloat16 As[2 * AS_BUF];
    __shared__ __align__(16) __nv_bfloat16 Bs[2 * BS_BUF];

    const __nv_bfloat16* A = (asel == 0) ? g_Ain : g_h[asel - 1];
    const __nv_bfloat16* W = ((wsel == 0) ? g_Win : g_Wh) + woff;
    __nv_bfloat16* C = g_h[csel];

    int bm0 = blockIdx.x * 128;
    int bn0 = blockIdx.y * 64;

    float acc[2][4][4] = {};
    gemm_mainloop(A, W, K, N, bm0, bn0, As, Bs, acc);

    const int lane = threadIdx.x & 31;
    const int warp = threadIdx.x >> 5;
    const int wm = warp & 3, wn = warp >> 2;

    #pragma unroll
    for (int m = 0; m < 2; ++m)
        #pragma unroll
        for (int nt = 0; nt < 4; ++nt) {
            int gr = bm0 + wm * 32 + m * 16 + (lane >> 2);
            int gc = bn0 + wn * 32 + nt * 8 + (lane & 3) * 2;
            float b0 = bias[gc], b1 = bias[gc + 1];
            float v0 = fmaxf(acc[m][nt][0] + b0, 0.f);
            float v1 = fmaxf(acc[m][nt][1] + b1, 0.f);
            float v2 = fmaxf(acc[m][nt][2] + b0, 0.f);
            float v3 = fmaxf(acc[m][nt][3] + b1, 0.f);
            __nv_bfloat162 p0, p1;
            p0.x = __float2bfloat16(v0); p0.y = __float2bfloat16(v1);
            p1.x = __float2bfloat16(v2); p1.y = __float2bfloat16(v3);
            *reinterpret_cast<__nv_bfloat162*>(C + (long)gr * N + gc) = p0;
            *reinterpret_cast<__nv_bfloat162*>(C + (long)(gr + 8) * N + gc) = p1;
        }
}

// ---------------- final GEMM of a layer + flow epilogue ----------------
#define PS_STRIDE 65
__global__ void __launch_bounds__(256)
gemm_out_kernel(int hsel, long woff, const float* __restrict__ bias,
                int layer, const int* __restrict__ perm, float* __restrict__ d_out)
{
    // union: GEMM staging (As 20480B + Bs 10240B) vs p-buffer (128*65*4 = 33280B)
    __shared__ __align__(16) char smraw[128 * PS_STRIDE * 4];
    __shared__ int sperm[64];
    __nv_bfloat16* As = (__nv_bfloat16*)smraw;
    __nv_bfloat16* Bs = (__nv_bfloat16*)(smraw + 2 * AS_BUF * 2);
    float* ps = (float*)smraw;

    if (perm && threadIdx.x < 64) sperm[threadIdx.x] = perm[threadIdx.x];

    const __nv_bfloat16* A = g_h[hsel];
    const __nv_bfloat16* W = g_Wout + woff;
    int bm0 = blockIdx.x * 128;

    float acc[2][4][4] = {};
    gemm_mainloop(A, W, HID, FDIM, bm0, 0, As, Bs, acc);
    __syncthreads();  // everyone done with As/Bs before ps overwrites them

    const int lane = threadIdx.x & 31;
    const int warp = threadIdx.x >> 5;
    const int wm = warp & 3, wn = warp >> 2;

    #pragma unroll
    for (int m = 0; m < 2; ++m)
        #pragma unroll
        for (int nt = 0; nt < 4; ++nt) {
            int r = wm * 32 + m * 16 + (lane >> 2);
            int c = wn * 32 + nt * 8 + (lane & 3) * 2;
            float b0 = bias[c], b1 = bias[c + 1];
            ps[r * PS_STRIDE + c]             = acc[m][nt][0] + b0;
            ps[r * PS_STRIDE + c + 1]         = acc[m][nt][1] + b1;
            ps[(r + 8) * PS_STRIDE + c]       = acc[m][nt][2] + b0;
            ps[(r + 8) * PS_STRIDE + c + 1]   = acc[m][nt][3] + b1;
        }
    __syncthreads();

    if (threadIdx.x < 128) {
        int  r  = threadIdx.x;
        long gr = bm0 + r;
        const float* xc = g_x[layer & 1] + gr * FDIM;
        float* prow = ps + r * PS_STRIDE;
        const int toff = layer & 1;  // layer even -> transform even cols

        float scale[32], shift[32];
        float ld = 0.f;
        #pragma unroll
        for (int k = 0; k < 32; ++k) {
            shift[k] = prow[k];
            float s  = prow[32 + k];
            scale[k] = 1.f / (1.f + expf(-(s + 2.f))) + 0.001f;
            ld += logf(scale[k]);
        }
        // build x_new in natural column order (overwrite prow)
        #pragma unroll
        for (int k = 0; k < 32; ++k) {
            int t  = 2 * k + toff;
            int id = 2 * k + 1 - toff;
            float xt = xc[t] * scale[k] + shift[k];
            float xi = xc[id];
            prow[t]  = xt;
            prow[id] = xi;
        }

        if (perm) {
            g_logdet[gr] += ld;
            float* xn = g_x[(layer & 1) ^ 1] + gr * FDIM;
            const int idoff = layer & 1;  // next layer's identity-col offset
            #pragma unroll
            for (int j = 0; j < 64; ++j) xn[j] = prow[sperm[j]];
            #pragma unroll
            for (int k = 0; k < 32; ++k)
                g_Ain[gr * KIN + k] = __float2bfloat16(prow[sperm[2 * k + idoff]]);
        } else {
            float tot = g_logdet[gr] + ld;
            #pragma unroll
            for (int j = 0; j < 64; ++j) {
                float v = prow[j];
                v = fminf(fmaxf(v, -1.f), 1.f);
                d_out[gr * FDIM + j] = v;
            }
            d_out[(long)BATCH * FDIM + gr] = tot;
        }
    }
}

// ---------------- init: x0 = clip(inputs), build A_in(layer0), zero logdet ----------------
__global__ void init_kernel(const float* __restrict__ inputs,
                            const float* __restrict__ context)
{
    int r = blockIdx.x * 4 + threadIdx.y;
    int c = threadIdx.x;  // 0..63
    __shared__ float xs[4][64];

    float v = inputs[(long)r * FDIM + c];
    v = fminf(fmaxf(v, -1.f), 1.f);
    g_x[0][(long)r * FDIM + c] = v;
    xs[threadIdx.y][c] = v;

    g_Ain[(long)r * KIN + 32 + c]      = __float2bfloat16(context[(long)r * CTXD + c]);
    g_Ain[(long)r * KIN + 32 + 64 + c] = __float2bfloat16(context[(long)r * CTXD + 64 + c]);
    __syncthreads();
    if (c < 32)  // layer 0: identity = odd columns
        g_Ain[(long)r * KIN + c] = __float2bfloat16(xs[threadIdx.y][2 * c + 1]);
    if (c == 0) g_logdet[r] = 0.f;
}

// ---------------- weight fp32 -> bf16 ----------------
__global__ void cvt_kernel(const float* __restrict__ win,
                           const float* __restrict__ wh,
                           const float* __restrict__ wout)
{
    const long n1 = (long)NLAYERS * KIN * HID;
    const long n2 = (long)NLAYERS * NBLK * HID * HID;
    const long n3 = (long)NLAYERS * HID * FDIM;
    const long total = n1 + n2 + n3;
    for (long i = (long)blockIdx.x * blockDim.x + threadIdx.x; i < total;
         i += (long)gridDim.x * blockDim.x) {
        if (i < n1)            g_Win[i]           = __float2bfloat16(win[i]);
        else if (i < n1 + n2)  g_Wh[i - n1]       = __float2bfloat16(wh[i - n1]);
        else                   g_Wout[i - n1 - n2]= __float2bfloat16(wout[i - n1 - n2]);
    }
}

// ---------------- launch ----------------
extern "C" void kernel_launch(void* const* d_in, const int* in_sizes, int n_in,
                              void* d_out, int out_size)
{
    const float* inputs  = (const float*)d_in[0];
    const float* context = (const float*)d_in[1];
    const float* W_in    = (const float*)d_in[2];
    const float* b_in    = (const float*)d_in[3];
    const float* W_h     = (const float*)d_in[4];
    const float* b_h     = (const float*)d_in[5];
    const float* W_out   = (const float*)d_in[6];
    const float* b_out   = (const float*)d_in[7];
    const int*   perms   = (const int*)d_in[8];
    float* out = (float*)d_out;

    cvt_kernel<<<2048, 256>>>(W_in, W_h, W_out);
    init_kernel<<<BATCH / 4, dim3(64, 4)>>>(inputs, context);

    for (int i = 0; i < NLAYERS; ++i) {
        // h0 = relu([id, ctx] @ W_in[i] + b_in[i])
        gemm_relu_kernel<<<dim3(BATCH / 128, HID / 64), 256>>>(
            0, 0, 0, (long)i * KIN * HID, b_in + i * HID, KIN, HID);
        // h1 = relu(h0 @ W_h[i,0] + b)
        gemm_relu_kernel<<<dim3(BATCH / 128, HID / 64), 256>>>(
            1, 1, 1, (long)(i * NBLK + 0) * HID * HID, b_h + (i * NBLK + 0) * HID, HID, HID);
        // h0 = relu(h1 @ W_h[i,1] + b)
        gemm_relu_kernel<<<dim3(BATCH / 128, HID / 64), 256>>>(
            2, 0, 1, (long)(i * NBLK + 1) * HID * HID, b_h + (i * NBLK + 1) * HID, HID, HID);
        // p = h0 @ W_out[i] + b_out[i]; flow epilogue + permutation (+final output)
        const int* p = (i < NLAYERS - 1) ? (perms + i * FDIM) : (const int*)nullptr;
        gemm_out_kernel<<<BATCH / 128, 256>>>(
            0, (long)i * HID * FDIM, b_out + i * FDIM, i, p, out);
    }
}

// round 11
// speedup vs baseline: 1.1666x; 1.1578x over previous
#include <cuda_runtime.h>
#include <cuda_bf16.h>
#include <math.h>

#define BATCH   16384
#define FDIM    64
#define CTXD    128
#define HID     512
#define NLAYERS 8
#define NBLK    2
#define KIN     160    // 32 id cols + 128 context cols
#define KINP    192    // padded to multiple of 64

// ---------------- scratch (device globals; no allocs allowed) ----------------
__device__ __align__(16) float         g_x[2][BATCH * FDIM];
__device__ __align__(16) float         g_logdet[BATCH];
__device__ __align__(16) __nv_bfloat16 g_Ain[BATCH * KINP];
__device__ __align__(16) __nv_bfloat16 g_h[2][BATCH * HID];
__device__ __align__(16) __nv_bfloat16 g_Win[NLAYERS * KINP * HID];
__device__ __align__(16) __nv_bfloat16 g_Wh[NLAYERS * NBLK * HID * HID];
__device__ __align__(16) __nv_bfloat16 g_Wout[NLAYERS * HID * FDIM];

// ---------------- PTX helpers ----------------
__device__ __forceinline__ unsigned smem_u32(const void* p) {
    return (unsigned)__cvta_generic_to_shared(p);
}
__device__ __forceinline__ void cp16(void* s, const void* g) {
    asm volatile("cp.async.cg.shared.global [%0], [%1], 16;\n"
                 :: "r"(smem_u32(s)), "l"(g));
}
__device__ __forceinline__ void cp_commit() { asm volatile("cp.async.commit_group;\n" ::); }
__device__ __forceinline__ void cp_wait0()  { asm volatile("cp.async.wait_group 0;\n" ::); }
__device__ __forceinline__ void cp_wait1()  { asm volatile("cp.async.wait_group 1;\n" ::); }

__device__ __forceinline__ void ldmA(unsigned* r, const void* p) {
    asm volatile("ldmatrix.sync.aligned.m8n8.x4.shared.b16 {%0,%1,%2,%3}, [%4];\n"
                 : "=r"(r[0]), "=r"(r[1]), "=r"(r[2]), "=r"(r[3])
                 : "r"(smem_u32(p)));
}
__device__ __forceinline__ void ldmBT(unsigned* r, const void* p) {
    asm volatile("ldmatrix.sync.aligned.m8n8.x4.trans.shared.b16 {%0,%1,%2,%3}, [%4];\n"
                 : "=r"(r[0]), "=r"(r[1]), "=r"(r[2]), "=r"(r[3])
                 : "r"(smem_u32(p)));
}
__device__ __forceinline__ void mma16816(float* d, const unsigned* a, unsigned b0, unsigned b1) {
    asm volatile("mma.sync.aligned.m16n8k16.row.col.f32.bf16.bf16.f32 "
                 "{%0,%1,%2,%3}, {%4,%5,%6,%7}, {%8,%9}, {%0,%1,%2,%3};\n"
                 : "+f"(d[0]), "+f"(d[1]), "+f"(d[2]), "+f"(d[3])
                 : "r"(a[0]), "r"(a[1]), "r"(a[2]), "r"(a[3]), "r"(b0), "r"(b1));
}

// ======================================================================
// Big GEMM: C(16384 x 512) = relu(A(16384 x K) @ W(K x 512) + bias)
// CTA tile 128x128, BK=64, 3-stage cp.async pipeline.
// 8 warps in 4(M) x 2(N); warp tile 32x64.
// ======================================================================
#define A2_STRIDE 72    // 64 cols + pad (row = 144B -> conflict-free ldmatrix)
#define B2_STRIDE 136   // 128 cols + pad (row = 272B -> conflict-free ldmatrix)
#define A2_BUF (128 * A2_STRIDE)
#define B2_BUF (64 * B2_STRIDE)
#define GSTAGES 3
#define GEMM128_SMEM (GSTAGES * (A2_BUF + B2_BUF) * 2)  // 107520 bytes

__global__ void __launch_bounds__(256, 2)
gemm128_kernel(int asel, int csel, int wsel, long woff,
               const float* __restrict__ bias, int K)
{
    extern __shared__ __align__(16) char dynsm[];
    __nv_bfloat16* As = (__nv_bfloat16*)dynsm;
    __nv_bfloat16* Bs = As + GSTAGES * A2_BUF;

    const __nv_bfloat16* A = (asel == 0) ? g_Ain : g_h[asel - 1];
    const __nv_bfloat16* W = ((wsel == 0) ? g_Win : g_Wh) + woff;
    __nv_bfloat16* C = g_h[csel];
    const int N = HID;

    const int bm0 = blockIdx.x * 128;
    const int bn0 = blockIdx.y * 128;
    const int tid  = threadIdx.x;
    const int lane = tid & 31;
    const int warp = tid >> 5;
    const int wm   = warp & 3;
    const int wn   = warp >> 2;

    const int KT = K >> 6;  // BK = 64

    auto load_tile = [&](int kt, int buf) {
        const __nv_bfloat16* Ag = A + (long)bm0 * K + kt * 64;
        __nv_bfloat16* as = As + buf * A2_BUF;
        #pragma unroll
        for (int it = 0; it < 4; ++it) {
            int c = tid + it * 256;
            int row = c >> 3;          // 8 chunks of 16B per 64-col row
            int co  = (c & 7) * 8;
            cp16(as + row * A2_STRIDE + co, Ag + (long)row * K + co);
        }
        const __nv_bfloat16* Wg = W + (long)(kt * 64) * N + bn0;
        __nv_bfloat16* bs = Bs + buf * B2_BUF;
        #pragma unroll
        for (int it = 0; it < 4; ++it) {
            int c = tid + it * 256;
            int row = c >> 4;          // 16 chunks per 128-col row
            int co  = (c & 15) * 8;
            cp16(bs + row * B2_STRIDE + co, Wg + (long)row * N + co);
        }
    };

    float acc[2][8][4] = {};

    load_tile(0, 0); cp_commit();
    load_tile(1, 1); cp_commit();

    for (int kt = 0; kt < KT; ++kt) {
        cp_wait1();             // stage kt has landed (kt+1 may still be in flight)
        __syncthreads();
        if (kt + 2 < KT) load_tile(kt + 2, (kt + 2) % GSTAGES);
        cp_commit();            // always commit (empty groups keep counting consistent)

        const __nv_bfloat16* as = As + (kt % GSTAGES) * A2_BUF;
        const __nv_bfloat16* bs = Bs + (kt % GSTAGES) * B2_BUF;

        #pragma unroll
        for (int ks = 0; ks < 4; ++ks) {
            unsigned a[2][4], bq[4][4];
            int ar = wm * 32 + (lane & 15);
            int ac = ks * 16 + (lane >> 4) * 8;
            ldmA(a[0], as + ar * A2_STRIDE + ac);
            ldmA(a[1], as + (ar + 16) * A2_STRIDE + ac);
            int br = ks * 16 + (lane & 15);
            #pragma unroll
            for (int nb = 0; nb < 4; ++nb)
                ldmBT(bq[nb], bs + br * B2_STRIDE + wn * 64 + nb * 16 + (lane >> 4) * 8);
            #pragma unroll
            for (int m = 0; m < 2; ++m)
                #pragma unroll
                for (int nb = 0; nb < 4; ++nb) {
                    mma16816(acc[m][nb * 2 + 0], a[m], bq[nb][0], bq[nb][1]);
                    mma16816(acc[m][nb * 2 + 1], a[m], bq[nb][2], bq[nb][3]);
                }
        }
    }

    // epilogue: bias + relu -> bf16
    #pragma unroll
    for (int m = 0; m < 2; ++m)
        #pragma unroll
        for (int nt = 0; nt < 8; ++nt) {
            int gr = bm0 + wm * 32 + m * 16 + (lane >> 2);
            int gc = bn0 + wn * 64 + nt * 8 + (lane & 3) * 2;
            float b0 = bias[gc], b1 = bias[gc + 1];
            float v0 = fmaxf(acc[m][nt][0] + b0, 0.f);
            float v1 = fmaxf(acc[m][nt][1] + b1, 0.f);
            float v2 = fmaxf(acc[m][nt][2] + b0, 0.f);
            float v3 = fmaxf(acc[m][nt][3] + b1, 0.f);
            __nv_bfloat162 p0, p1;
            p0.x = __float2bfloat16(v0); p0.y = __float2bfloat16(v1);
            p1.x = __float2bfloat16(v2); p1.y = __float2bfloat16(v3);
            *reinterpret_cast<__nv_bfloat162*>(C + (long)gr * N + gc) = p0;
            *reinterpret_cast<__nv_bfloat162*>(C + (long)(gr + 8) * N + gc) = p1;
        }
}

// ======================================================================
// Small out-GEMM (128x64 tile, BK=32, 2 stages) + flow epilogue
// ======================================================================
#define AS_STRIDE 40
#define BS_STRIDE 80
#define AS_BUF (128 * AS_STRIDE)
#define BS_BUF (32 * BS_STRIDE)

__device__ __forceinline__ void gemm_mainloop64(
    const __nv_bfloat16* A, const __nv_bfloat16* W, int K, int N,
    int bm0, int bn0, __nv_bfloat16* As, __nv_bfloat16* Bs,
    float acc[2][4][4])
{
    const int tid  = threadIdx.x;
    const int lane = tid & 31;
    const int warp = tid >> 5;
    const int wm   = warp & 3;
    const int wn   = warp >> 2;
    const int KT = K >> 5;

    auto load_tile = [&](int kt, int buf) {
        const __nv_bfloat16* Ag = A + (long)bm0 * K + kt * 32;
        #pragma unroll
        for (int it = 0; it < 2; ++it) {
            int c   = tid + it * 256;
            int row = c >> 2;
            int co  = (c & 3) * 8;
            cp16(As + buf * AS_BUF + row * AS_STRIDE + co, Ag + (long)row * K + co);
        }
        {
            int row = tid >> 3;
            int co  = (tid & 7) * 8;
            cp16(Bs + buf * BS_BUF + row * BS_STRIDE + co,
                 W + (long)(kt * 32 + row) * N + bn0 + co);
        }
    };

    load_tile(0, 0);
    cp_commit();

    for (int kt = 0; kt < KT; ++kt) {
        cp_wait0();
        __syncthreads();
        if (kt + 1 < KT) load_tile(kt + 1, (kt + 1) & 1);
        cp_commit();

        const __nv_bfloat16* as = As + (kt & 1) * AS_BUF;
        const __nv_bfloat16* bs = Bs + (kt & 1) * BS_BUF;

        #pragma unroll
        for (int ks = 0; ks < 2; ++ks) {
            unsigned a[2][4], bq[2][4];
            int ar = wm * 32 + (lane & 15);
            int ac = ks * 16 + (lane >> 4) * 8;
            ldmA(a[0], as + ar * AS_STRIDE + ac);
            ldmA(a[1], as + (ar + 16) * AS_STRIDE + ac);
            int br = ks * 16 + (lane & 15);
            ldmBT(bq[0], bs + br * BS_STRIDE + wn * 32 + 0  + (lane >> 4) * 8);
            ldmBT(bq[1], bs + br * BS_STRIDE + wn * 32 + 16 + (lane >> 4) * 8);
            #pragma unroll
            for (int m = 0; m < 2; ++m)
                #pragma unroll
                for (int nb = 0; nb < 2; ++nb) {
                    mma16816(acc[m][nb * 2 + 0], a[m], bq[nb][0], bq[nb][1]);
                    mma16816(acc[m][nb * 2 + 1], a[m], bq[nb][2], bq[nb][3]);
                }
        }
    }
}

#define PS_STRIDE 65
__global__ void __launch_bounds__(256)
gemm_out_kernel(int hsel, long woff, const float* __restrict__ bias,
                int layer, const int* __restrict__ perm, float* __restrict__ d_out)
{
    __shared__ __align__(16) char smraw[128 * PS_STRIDE * 4];
    __shared__ int sperm[64];
    __nv_bfloat16* As = (__nv_bfloat16*)smraw;
    __nv_bfloat16* Bs = (__nv_bfloat16*)(smraw + 2 * AS_BUF * 2);
    float* ps = (float*)smraw;

    if (perm && threadIdx.x < 64) sperm[threadIdx.x] = perm[threadIdx.x];

    const __nv_bfloat16* A = g_h[hsel];
    const __nv_bfloat16* W = g_Wout + woff;
    int bm0 = blockIdx.x * 128;

    float acc[2][4][4] = {};
    gemm_mainloop64(A, W, HID, FDIM, bm0, 0, As, Bs, acc);
    __syncthreads();

    const int lane = threadIdx.x & 31;
    const int warp = threadIdx.x >> 5;
    const int wm = warp & 3, wn = warp >> 2;

    #pragma unroll
    for (int m = 0; m < 2; ++m)
        #pragma unroll
        for (int nt = 0; nt < 4; ++nt) {
            int r = wm * 32 + m * 16 + (lane >> 2);
            int c = wn * 32 + nt * 8 + (lane & 3) * 2;
            float b0 = bias[c], b1 = bias[c + 1];
            ps[r * PS_STRIDE + c]           = acc[m][nt][0] + b0;
            ps[r * PS_STRIDE + c + 1]       = acc[m][nt][1] + b1;
            ps[(r + 8) * PS_STRIDE + c]     = acc[m][nt][2] + b0;
            ps[(r + 8) * PS_STRIDE + c + 1] = acc[m][nt][3] + b1;
        }
    __syncthreads();

    if (threadIdx.x < 128) {
        int  r  = threadIdx.x;
        long gr = bm0 + r;
        const float* xc = g_x[layer & 1] + gr * FDIM;
        float* prow = ps + r * PS_STRIDE;
        const int toff = layer & 1;

        float scale[32], shift[32];
        float ld = 0.f;
        #pragma unroll
        for (int k = 0; k < 32; ++k) {
            shift[k] = prow[k];
            float s  = prow[32 + k];
            scale[k] = 1.f / (1.f + expf(-(s + 2.f))) + 0.001f;
            ld += logf(scale[k]);
        }
        #pragma unroll
        for (int k = 0; k < 32; ++k) {
            int t  = 2 * k + toff;
            int id = 2 * k + 1 - toff;
            float xt = xc[t] * scale[k] + shift[k];
            float xi = xc[id];
            prow[t]  = xt;
            prow[id] = xi;
        }

        if (perm) {
            g_logdet[gr] += ld;
            float* xn = g_x[(layer & 1) ^ 1] + gr * FDIM;
            const int idoff = layer & 1;
            #pragma unroll
            for (int j = 0; j < 64; ++j) xn[j] = prow[sperm[j]];
            #pragma unroll
            for (int k = 0; k < 32; ++k)
                g_Ain[gr * KINP + k] = __float2bfloat16(prow[sperm[2 * k + idoff]]);
        } else {
            float tot = g_logdet[gr] + ld;
            #pragma unroll
            for (int j = 0; j < 64; ++j) {
                float v = prow[j];
                v = fminf(fmaxf(v, -1.f), 1.f);
                d_out[gr * FDIM + j] = v;
            }
            d_out[(long)BATCH * FDIM + gr] = tot;
        }
    }
}

// ---------------- init: x0 = clip(inputs), build A_in(layer0), zero logdet ----------------
__global__ void init_kernel(const float* __restrict__ inputs,
                            const float* __restrict__ context)
{
    int r = blockIdx.x * 4 + threadIdx.y;
    int c = threadIdx.x;  // 0..63
    __shared__ float xs[4][64];

    float v = inputs[(long)r * FDIM + c];
    v = fminf(fmaxf(v, -1.f), 1.f);
    g_x[0][(long)r * FDIM + c] = v;
    xs[threadIdx.y][c] = v;

    g_Ain[(long)r * KINP + 32 + c]      = __float2bfloat16(context[(long)r * CTXD + c]);
    g_Ain[(long)r * KINP + 32 + 64 + c] = __float2bfloat16(context[(long)r * CTXD + 64 + c]);
    if (c < 32)  // K padding (cols 160..191) stays zero
        g_Ain[(long)r * KINP + KIN + c] = __float2bfloat16(0.f);
    __syncthreads();
    if (c < 32)  // layer 0: identity = odd columns
        g_Ain[(long)r * KINP + c] = __float2bfloat16(xs[threadIdx.y][2 * c + 1]);
    if (c == 0) g_logdet[r] = 0.f;
}

// ---------------- weight fp32 -> bf16 (W_in K-padded to 192) ----------------
__global__ void cvt_kernel(const float* __restrict__ win,
                           const float* __restrict__ wh,
                           const float* __restrict__ wout)
{
    const long n1 = (long)NLAYERS * KINP * HID;
    const long n2 = (long)NLAYERS * NBLK * HID * HID;
    const long n3 = (long)NLAYERS * HID * FDIM;
    const long total = n1 + n2 + n3;
    for (long i = (long)blockIdx.x * blockDim.x + threadIdx.x; i < total;
         i += (long)gridDim.x * blockDim.x) {
        if (i < n1) {
            long l = i / ((long)KINP * HID);
            long r = (i / HID) % KINP;
            long c = i % HID;
            g_Win[i] = (r < KIN) ? __float2bfloat16(win[(l * KIN + r) * HID + c])
                                 : __float2bfloat16(0.f);
        } else if (i < n1 + n2) {
            g_Wh[i - n1] = __float2bfloat16(wh[i - n1]);
        } else {
            g_Wout[i - n1 - n2] = __float2bfloat16(wout[i - n1 - n2]);
        }
    }
}

// ---------------- launch ----------------
extern "C" void kernel_launch(void* const* d_in, const int* in_sizes, int n_in,
                              void* d_out, int out_size)
{
    const float* inputs  = (const float*)d_in[0];
    const float* context = (const float*)d_in[1];
    const float* W_in    = (const float*)d_in[2];
    const float* b_in    = (const float*)d_in[3];
    const float* W_h     = (const float*)d_in[4];
    const float* b_h     = (const float*)d_in[5];
    const float* W_out   = (const float*)d_in[6];
    const float* b_out   = (const float*)d_in[7];
    const int*   perms   = (const int*)d_in[8];
    float* out = (float*)d_out;

    cudaFuncSetAttribute(gemm128_kernel,
                         cudaFuncAttributeMaxDynamicSharedMemorySize, GEMM128_SMEM);

    cvt_kernel<<<2048, 256>>>(W_in, W_h, W_out);
    init_kernel<<<BATCH / 4, dim3(64, 4)>>>(inputs, context);

    dim3 gg(BATCH / 128, HID / 128);
    for (int i = 0; i < NLAYERS; ++i) {
        // h0 = relu([id, ctx, pad] @ W_in[i] + b_in[i]), K = 192
        gemm128_kernel<<<gg, 256, GEMM128_SMEM>>>(
            0, 0, 0, (long)i * KINP * HID, b_in + i * HID, KINP);
        // h1 = relu(h0 @ W_h[i,0] + b)
        gemm128_kernel<<<gg, 256, GEMM128_SMEM>>>(
            1, 1, 1, (long)(i * NBLK + 0) * HID * HID, b_h + (i * NBLK + 0) * HID, HID);
        // h0 = relu(h1 @ W_h[i,1] + b)
        gemm128_kernel<<<gg, 256, GEMM128_SMEM>>>(
            2, 0, 1, (long)(i * NBLK + 1) * HID * HID, b_h + (i * NBLK + 1) * HID, HID);
        // p = h0 @ W_out[i] + b_out[i]; flow epilogue + permutation (+final output)
        const int* p = (i < NLAYERS - 1) ? (perms + i * FDIM) : (const int*)nullptr;
        gemm_out_kernel<<<BATCH / 128, 256>>>(
            0, (long)i * HID * FDIM, b_out + i * FDIM, i, p, out);
    }
}

// round 13
// speedup vs baseline: 1.1829x; 1.0140x over previous
#include <cuda_runtime.h>
#include <cuda_bf16.h>
#include <math.h>

#define BATCH   16384
#define FDIM    64
#define CTXD    128
#define HID     512
#define NLAYERS 8
#define NBLK    2
#define KIN     160    // 32 id cols + 128 context cols
#define KINP    192    // padded to multiple of 64

// ---------------- scratch (device globals; no allocs allowed) ----------------
__device__ __align__(16) float         g_x[2][BATCH * FDIM];
__device__ __align__(16) float         g_logdet[BATCH];
__device__ __align__(16) __nv_bfloat16 g_Ain[BATCH * KINP];
__device__ __align__(16) __nv_bfloat16 g_h[2][BATCH * HID];
__device__ __align__(16) __nv_bfloat16 g_Win[NLAYERS * KINP * HID];
__device__ __align__(16) __nv_bfloat16 g_Wh[NLAYERS * NBLK * HID * HID];
__device__ __align__(16) __nv_bfloat16 g_Wout[NLAYERS * HID * FDIM];

// ---------------- PTX helpers ----------------
__device__ __forceinline__ unsigned smem_u32(const void* p) {
    return (unsigned)__cvta_generic_to_shared(p);
}
__device__ __forceinline__ void cp16(void* s, const void* g) {
    asm volatile("cp.async.cg.shared.global [%0], [%1], 16;\n"
                 :: "r"(smem_u32(s)), "l"(g));
}
__device__ __forceinline__ void cp_commit() { asm volatile("cp.async.commit_group;\n" ::); }
__device__ __forceinline__ void cp_wait0()  { asm volatile("cp.async.wait_group 0;\n" ::); }
__device__ __forceinline__ void cp_wait1()  { asm volatile("cp.async.wait_group 1;\n" ::); }

__device__ __forceinline__ void ldmA(unsigned* r, const void* p) {
    asm volatile("ldmatrix.sync.aligned.m8n8.x4.shared.b16 {%0,%1,%2,%3}, [%4];\n"
                 : "=r"(r[0]), "=r"(r[1]), "=r"(r[2]), "=r"(r[3])
                 : "r"(smem_u32(p)));
}
__device__ __forceinline__ void ldmBT(unsigned* r, const void* p) {
    asm volatile("ldmatrix.sync.aligned.m8n8.x4.trans.shared.b16 {%0,%1,%2,%3}, [%4];\n"
                 : "=r"(r[0]), "=r"(r[1]), "=r"(r[2]), "=r"(r[3])
                 : "r"(smem_u32(p)));
}
__device__ __forceinline__ void mma16816(float* d, const unsigned* a, unsigned b0, unsigned b1) {
    asm volatile("mma.sync.aligned.m16n8k16.row.col.f32.bf16.bf16.f32 "
                 "{%0,%1,%2,%3}, {%4,%5,%6,%7}, {%8,%9}, {%0,%1,%2,%3};\n"
                 : "+f"(d[0]), "+f"(d[1]), "+f"(d[2]), "+f"(d[3])
                 : "r"(a[0]), "r"(a[1]), "r"(a[2]), "r"(a[3]), "r"(b0), "r"(b1));
}

// ======================================================================
// Big GEMM: C(16384 x 512) = relu(A(16384 x K) @ W(K x 512) + bias)
// CTA tile 128x128, BK=64, 3-stage cp.async pipeline.  (R11-measured: 36.5us)
// 8 warps in 4(M) x 2(N); warp tile 32x64.
// ======================================================================
#define A2_STRIDE 72    // 64 cols + pad (row = 144B -> conflict-free ldmatrix)
#define B2_STRIDE 136   // 128 cols + pad (row = 272B -> conflict-free ldmatrix)
#define A2_BUF (128 * A2_STRIDE)
#define B2_BUF (64 * B2_STRIDE)
#define GSTAGES 3
#define GEMM128_SMEM (GSTAGES * (A2_BUF + B2_BUF) * 2)  // 107520 bytes

__global__ void __launch_bounds__(256, 2)
gemm128_kernel(int asel, int csel, int wsel, long woff,
               const float* __restrict__ bias, int K)
{
    extern __shared__ __align__(16) char dynsm[];
    __nv_bfloat16* As = (__nv_bfloat16*)dynsm;
    __nv_bfloat16* Bs = As + GSTAGES * A2_BUF;

    const __nv_bfloat16* A = (asel == 0) ? g_Ain : g_h[asel - 1];
    const __nv_bfloat16* W = ((wsel == 0) ? g_Win : g_Wh) + woff;
    __nv_bfloat16* C = g_h[csel];
    const int N = HID;

    const int bm0 = blockIdx.x * 128;
    const int bn0 = blockIdx.y * 128;
    const int tid  = threadIdx.x;
    const int lane = tid & 31;
    const int warp = tid >> 5;
    const int wm   = warp & 3;
    const int wn   = warp >> 2;

    const int KT = K >> 6;  // BK = 64

    auto load_tile = [&](int kt, int buf) {
        const __nv_bfloat16* Ag = A + (long)bm0 * K + kt * 64;
        __nv_bfloat16* as = As + buf * A2_BUF;
        #pragma unroll
        for (int it = 0; it < 4; ++it) {
            int c = tid + it * 256;
            int row = c >> 3;          // 8 chunks of 16B per 64-col row
            int co  = (c & 7) * 8;
            cp16(as + row * A2_STRIDE + co, Ag + (long)row * K + co);
        }
        const __nv_bfloat16* Wg = W + (long)(kt * 64) * N + bn0;
        __nv_bfloat16* bs = Bs + buf * B2_BUF;
        #pragma unroll
        for (int it = 0; it < 4; ++it) {
            int c = tid + it * 256;
            int row = c >> 4;          // 16 chunks per 128-col row
            int co  = (c & 15) * 8;
            cp16(bs + row * B2_STRIDE + co, Wg + (long)row * N + co);
        }
    };

    float acc[2][8][4] = {};

    load_tile(0, 0); cp_commit();
    load_tile(1, 1); cp_commit();

    for (int kt = 0; kt < KT; ++kt) {
        cp_wait1();             // stage kt has landed (kt+1 may still be in flight)
        __syncthreads();
        if (kt + 2 < KT) load_tile(kt + 2, (kt + 2) % GSTAGES);
        cp_commit();            // always commit (empty groups keep counting consistent)

        const __nv_bfloat16* as = As + (kt % GSTAGES) * A2_BUF;
        const __nv_bfloat16* bs = Bs + (kt % GSTAGES) * B2_BUF;

        #pragma unroll
        for (int ks = 0; ks < 4; ++ks) {
            unsigned a[2][4], bq[4][4];
            int ar = wm * 32 + (lane & 15);
            int ac = ks * 16 + (lane >> 4) * 8;
            ldmA(a[0], as + ar * A2_STRIDE + ac);
            ldmA(a[1], as + (ar + 16) * A2_STRIDE + ac);
            int br = ks * 16 + (lane & 15);
            #pragma unroll
            for (int nb = 0; nb < 4; ++nb)
                ldmBT(bq[nb], bs + br * B2_STRIDE + wn * 64 + nb * 16 + (lane >> 4) * 8);
            #pragma unroll
            for (int m = 0; m < 2; ++m)
                #pragma unroll
                for (int nb = 0; nb < 4; ++nb) {
                    mma16816(acc[m][nb * 2 + 0], a[m], bq[nb][0], bq[nb][1]);
                    mma16816(acc[m][nb * 2 + 1], a[m], bq[nb][2], bq[nb][3]);
                }
        }
    }

    // epilogue: bias + relu -> bf16
    #pragma unroll
    for (int m = 0; m < 2; ++m)
        #pragma unroll
        for (int nt = 0; nt < 8; ++nt) {
            int gr = bm0 + wm * 32 + m * 16 + (lane >> 2);
            int gc = bn0 + wn * 64 + nt * 8 + (lane & 3) * 2;
            float b0 = bias[gc], b1 = bias[gc + 1];
            float v0 = fmaxf(acc[m][nt][0] + b0, 0.f);
            float v1 = fmaxf(acc[m][nt][1] + b1, 0.f);
            float v2 = fmaxf(acc[m][nt][2] + b0, 0.f);
            float v3 = fmaxf(acc[m][nt][3] + b1, 0.f);
            __nv_bfloat162 p0, p1;
            p0.x = __float2bfloat16(v0); p0.y = __float2bfloat16(v1);
            p1.x = __float2bfloat16(v2); p1.y = __float2bfloat16(v3);
            *reinterpret_cast<__nv_bfloat162*>(C + (long)gr * N + gc) = p0;
            *reinterpret_cast<__nv_bfloat162*>(C + (long)(gr + 8) * N + gc) = p1;
        }
}

// ======================================================================
// Out-GEMM v2: BM=64, N=64, K=512, BK=64, 2 stages, 256 thr (8 warps 4Mx2N,
// warp tile 16x32, acc 16 regs) -> ~4 CTAs/SM, grid 256 in one wave.
// ======================================================================
#define AO_STRIDE 72                       // 64 cols + 8 pad (144B rows)
#define AO_BUF (64 * AO_STRIDE)            // A stage: 64 rows
#define BO_BUF (64 * AO_STRIDE)            // B stage: 64 k-rows x 64 n-cols
#define PS2_STRIDE 65

__global__ void __launch_bounds__(256)
gemm_out_kernel(int hsel, long woff, const float* __restrict__ bias,
                int layer, const int* __restrict__ perm, float* __restrict__ d_out)
{
    // union: GEMM staging (2 stages x (A+B) = 36864 B) vs ps (64*65*4 = 16640 B)
    __shared__ __align__(16) char smraw[2 * (AO_BUF + BO_BUF) * 2];
    __shared__ int sperm[64];
    __nv_bfloat16* As = (__nv_bfloat16*)smraw;                       // 2 stages
    __nv_bfloat16* Bs = (__nv_bfloat16*)smraw + 2 * AO_BUF;          // 2 stages
    float* ps = (float*)smraw;

    if (perm && threadIdx.x < 64) sperm[threadIdx.x] = perm[threadIdx.x];

    const __nv_bfloat16* A = g_h[hsel];
    const __nv_bfloat16* W = g_Wout + woff;   // [512 x 64]
    const int bm0 = blockIdx.x * 64;
    const int tid  = threadIdx.x;
    const int lane = tid & 31;
    const int warp = tid >> 5;
    const int wm   = warp & 3;                // M: 4 x 16 rows
    const int wn   = warp >> 2;               // N: 2 x 32 cols
    const int KT   = HID >> 6;                // 8 iters of BK=64

    auto load_tile = [&](int kt, int buf) {
        const __nv_bfloat16* Ag = A + (long)bm0 * HID + kt * 64;
        {   // A: 64 rows x 128B = 512 chunks, 2/thread
            #pragma unroll
            for (int it = 0; it < 2; ++it) {
                int c = tid + it * 256;
                int row = c >> 3;
                int co  = (c & 7) * 8;
                cp16(As + buf * AO_BUF + row * AO_STRIDE + co, Ag + (long)row * HID + co);
            }
        }
        {   // B: 64 k-rows x 128B = 512 chunks, 2/thread
            const __nv_bfloat16* Wg = W + (long)(kt * 64) * FDIM;
            #pragma unroll
            for (int it = 0; it < 2; ++it) {
                int c = tid + it * 256;
                int row = c >> 3;
                int co  = (c & 7) * 8;
                cp16(Bs + buf * BO_BUF + row * AO_STRIDE + co, Wg + (long)row * FDIM + co);
            }
        }
    };

    float acc[4][4] = {};

    load_tile(0, 0);
    cp_commit();

    for (int kt = 0; kt < KT; ++kt) {
        cp_wait0();
        __syncthreads();
        if (kt + 1 < KT) load_tile(kt + 1, (kt + 1) & 1);
        cp_commit();

        const __nv_bfloat16* as = As + (kt & 1) * AO_BUF;
        const __nv_bfloat16* bs = Bs + (kt & 1) * BO_BUF;

        #pragma unroll
        for (int ks = 0; ks < 4; ++ks) {
            unsigned a[4], bq[2][4];
            int ar = wm * 16 + (lane & 15);
            int ac = ks * 16 + (lane >> 4) * 8;
            ldmA(a, as + ar * AO_STRIDE + ac);
            int br = ks * 16 + (lane & 15);
            #pragma unroll
            for (int nb = 0; nb < 2; ++nb)
                ldmBT(bq[nb], bs + br * AO_STRIDE + wn * 32 + nb * 16 + (lane >> 4) * 8);
            #pragma unroll
            for (int nb = 0; nb < 2; ++nb) {
                mma16816(acc[nb * 2 + 0], a, bq[nb][0], bq[nb][1]);
                mma16816(acc[nb * 2 + 1], a, bq[nb][2], bq[nb][3]);
            }
        }
    }
    __syncthreads();   // everyone done with As/Bs before ps overwrites them

    #pragma unroll
    for (int nt = 0; nt < 4; ++nt) {
        int r = wm * 16 + (lane >> 2);
        int c = wn * 32 + nt * 8 + (lane & 3) * 2;
        float b0 = bias[c], b1 = bias[c + 1];
        ps[r * PS2_STRIDE + c]           = acc[nt][0] + b0;
        ps[r * PS2_STRIDE + c + 1]       = acc[nt][1] + b1;
        ps[(r + 8) * PS2_STRIDE + c]     = acc[nt][2] + b0;
        ps[(r + 8) * PS2_STRIDE + c + 1] = acc[nt][3] + b1;
    }
    __syncthreads();

    if (threadIdx.x < 64) {
        int  r  = threadIdx.x;
        long gr = bm0 + r;
        const float* xc = g_x[layer & 1] + gr * FDIM;
        float* prow = ps + r * PS2_STRIDE;
        const int toff = layer & 1;

        float scale[32], shift[32];
        float ld = 0.f;
        #pragma unroll
        for (int k = 0; k < 32; ++k) {
            shift[k] = prow[k];
            float s  = prow[32 + k];
            scale[k] = 1.f / (1.f + expf(-(s + 2.f))) + 0.001f;
            ld += logf(scale[k]);
        }
        #pragma unroll
        for (int k = 0; k < 32; ++k) {
            int t  = 2 * k + toff;
            int id = 2 * k + 1 - toff;
            float xt = xc[t] * scale[k] + shift[k];
            float xi = xc[id];
            prow[t]  = xt;
            prow[id] = xi;
        }

        if (perm) {
            g_logdet[gr] += ld;
            float* xn = g_x[(layer & 1) ^ 1] + gr * FDIM;
            const int idoff = layer & 1;
            #pragma unroll
            for (int j = 0; j < 64; ++j) xn[j] = prow[sperm[j]];
            #pragma unroll
            for (int k = 0; k < 32; ++k)
                g_Ain[gr * KINP + k] = __float2bfloat16(prow[sperm[2 * k + idoff]]);
        } else {
            float tot = g_logdet[gr] + ld;
            #pragma unroll
            for (int j = 0; j < 64; ++j) {
                float v = prow[j];
                v = fminf(fmaxf(v, -1.f), 1.f);
                d_out[gr * FDIM + j] = v;
            }
            d_out[(long)BATCH * FDIM + gr] = tot;
        }
    }
}

// ---------------- init: x0 = clip(inputs), build A_in(layer0), zero logdet ----------------
__global__ void init_kernel(const float* __restrict__ inputs,
                            const float* __restrict__ context)
{
    int r = blockIdx.x * 4 + threadIdx.y;
    int c = threadIdx.x;  // 0..63
    __shared__ float xs[4][64];

    float v = inputs[(long)r * FDIM + c];
    v = fminf(fmaxf(v, -1.f), 1.f);
    g_x[0][(long)r * FDIM + c] = v;
    xs[threadIdx.y][c] = v;

    g_Ain[(long)r * KINP + 32 + c]      = __float2bfloat16(context[(long)r * CTXD + c]);
    g_Ain[(long)r * KINP + 32 + 64 + c] = __float2bfloat16(context[(long)r * CTXD + 64 + c]);
    if (c < 32)  // K padding (cols 160..191) stays zero
        g_Ain[(long)r * KINP + KIN + c] = __float2bfloat16(0.f);
    __syncthreads();
    if (c < 32)  // layer 0: identity = odd columns
        g_Ain[(long)r * KINP + c] = __float2bfloat16(xs[threadIdx.y][2 * c + 1]);
    if (c == 0) g_logdet[r] = 0.f;
}

// ---------------- weight fp32 -> bf16 (W_in K-padded to 192) ----------------
__global__ void cvt_kernel(const float* __restrict__ win,
                           const float* __restrict__ wh,
                           const float* __restrict__ wout)
{
    const long n1 = (long)NLAYERS * KINP * HID;
    const long n2 = (long)NLAYERS * NBLK * HID * HID;
    const long n3 = (long)NLAYERS * HID * FDIM;
    const long total = n1 + n2 + n3;
    for (long i = (long)blockIdx.x * blockDim.x + threadIdx.x; i < total;
         i += (long)gridDim.x * blockDim.x) {
        if (i < n1) {
            long l = i / ((long)KINP * HID);
            long r = (i / HID) % KINP;
            long c = i % HID;
            g_Win[i] = (r < KIN) ? __float2bfloat16(win[(l * KIN + r) * HID + c])
                                 : __float2bfloat16(0.f);
        } else if (i < n1 + n2) {
            g_Wh[i - n1] = __float2bfloat16(wh[i - n1]);
        } else {
            g_Wout[i - n1 - n2] = __float2bfloat16(wout[i - n1 - n2]);
        }
    }
}

// ---------------- launch ----------------
extern "C" void kernel_launch(void* const* d_in, const int* in_sizes, int n_in,
                              void* d_out, int out_size)
{
    const float* inputs  = (const float*)d_in[0];
    const float* context = (const float*)d_in[1];
    const float* W_in    = (const float*)d_in[2];
    const float* b_in    = (const float*)d_in[3];
    const float* W_h     = (const float*)d_in[4];
    const float* b_h     = (const float*)d_in[5];
    const float* W_out   = (const float*)d_in[6];
    const float* b_out   = (const float*)d_in[7];
    const int*   perms   = (const int*)d_in[8];
    float* out = (float*)d_out;

    cudaFuncSetAttribute(gemm128_kernel,
                         cudaFuncAttributeMaxDynamicSharedMemorySize, GEMM128_SMEM);

    cvt_kernel<<<2048, 256>>>(W_in, W_h, W_out);
    init_kernel<<<BATCH / 4, dim3(64, 4)>>>(inputs, context);

    dim3 gg(BATCH / 128, HID / 128);
    for (int i = 0; i < NLAYERS; ++i) {
        // h0 = relu([id, ctx, pad] @ W_in[i] + b_in[i]), K = 192
        gemm128_kernel<<<gg, 256, GEMM128_SMEM>>>(
            0, 0, 0, (long)i * KINP * HID, b_in + i * HID, KINP);
        // h1 = relu(h0 @ W_h[i,0] + b)
        gemm128_kernel<<<gg, 256, GEMM128_SMEM>>>(
            1, 1, 1, (long)(i * NBLK + 0) * HID * HID, b_h + (i * NBLK + 0) * HID, HID);
        // h0 = relu(h1 @ W_h[i,1] + b)
        gemm128_kernel<<<gg, 256, GEMM128_SMEM>>>(
            2, 0, 1, (long)(i * NBLK + 1) * HID * HID, b_h + (i * NBLK + 1) * HID, HID);
        // p = h0 @ W_out[i] + b_out[i]; flow epilogue + permutation (+final output)
        const int* p = (i < NLAYERS - 1) ? (perms + i * FDIM) : (const int*)nullptr;
        gemm_out_kernel<<<BATCH / 64, 256>>>(
            0, (long)i * HID * FDIM, b_out + i * FDIM, i, p, out);
    }
}

// round 16
// speedup vs baseline: 1.2028x; 1.0168x over previous
#include <cuda_runtime.h>
#include <cuda_bf16.h>
#include <math.h>

#define BATCH   16384
#define FDIM    64
#define CTXD    128
#define HID     512
#define NLAYERS 8
#define NBLK    2
#define KIN     160    // 32 id cols + 128 context cols
#define KINP    192    // padded to multiple of 64

// ---------------- scratch (device globals; no allocs allowed) ----------------
__device__ __align__(16) float         g_x[2][BATCH * FDIM];
__device__ __align__(16) float         g_logdet[BATCH];
__device__ __align__(16) __nv_bfloat16 g_Ain[BATCH * KINP];
__device__ __align__(16) __nv_bfloat16 g_h[2][BATCH * HID];
__device__ __align__(16) __nv_bfloat16 g_Win[NLAYERS * KINP * HID];
__device__ __align__(16) __nv_bfloat16 g_Wh[NLAYERS * NBLK * HID * HID];
__device__ __align__(16) __nv_bfloat16 g_Wout[NLAYERS * HID * FDIM];

// ---------------- PTX helpers ----------------
__device__ __forceinline__ unsigned smem_u32(const void* p) {
    return (unsigned)__cvta_generic_to_shared(p);
}
__device__ __forceinline__ void cp16(void* s, const void* g) {
    asm volatile("cp.async.cg.shared.global [%0], [%1], 16;\n"
                 :: "r"(smem_u32(s)), "l"(g));
}
__device__ __forceinline__ void cp_commit() { asm volatile("cp.async.commit_group;\n" ::); }
__device__ __forceinline__ void cp_wait0()  { asm volatile("cp.async.wait_group 0;\n" ::); }
__device__ __forceinline__ void cp_wait1()  { asm volatile("cp.async.wait_group 1;\n" ::); }
__device__ __forceinline__ void cp_wait2()  { asm volatile("cp.async.wait_group 2;\n" ::); }

__device__ __forceinline__ void ldmA(unsigned* r, const void* p) {
    asm volatile("ldmatrix.sync.aligned.m8n8.x4.shared.b16 {%0,%1,%2,%3}, [%4];\n"
                 : "=r"(r[0]), "=r"(r[1]), "=r"(r[2]), "=r"(r[3])
                 : "r"(smem_u32(p)));
}
__device__ __forceinline__ void ldmBT(unsigned* r, const void* p) {
    asm volatile("ldmatrix.sync.aligned.m8n8.x4.trans.shared.b16 {%0,%1,%2,%3}, [%4];\n"
                 : "=r"(r[0]), "=r"(r[1]), "=r"(r[2]), "=r"(r[3])
                 : "r"(smem_u32(p)));
}
__device__ __forceinline__ void mma16816(float* d, const unsigned* a, unsigned b0, unsigned b1) {
    asm volatile("mma.sync.aligned.m16n8k16.row.col.f32.bf16.bf16.f32 "
                 "{%0,%1,%2,%3}, {%4,%5,%6,%7}, {%8,%9}, {%0,%1,%2,%3};\n"
                 : "+f"(d[0]), "+f"(d[1]), "+f"(d[2]), "+f"(d[3])
                 : "r"(a[0]), "r"(a[1]), "r"(a[2]), "r"(a[3]), "r"(b0), "r"(b1));
}

// ======================================================================
// Big GEMM: C(16384 x 512) = relu(A(16384 x K) @ W(K x 512) + bias)
// CTA tile 128x128, BK=64, 3-stage cp.async pipeline.  (measured: 37.0us)
// 8 warps in 4(M) x 2(N); warp tile 32x64.
// ======================================================================
#define A2_STRIDE 72    // 64 cols + pad (row = 144B -> conflict-free ldmatrix)
#define B2_STRIDE 136   // 128 cols + pad (row = 272B -> conflict-free ldmatrix)
#define A2_BUF (128 * A2_STRIDE)
#define B2_BUF (64 * B2_STRIDE)
#define GSTAGES 3
#define GEMM128_SMEM (GSTAGES * (A2_BUF + B2_BUF) * 2)  // 107520 bytes

__global__ void __launch_bounds__(256, 2)
gemm128_kernel(int asel, int csel, int wsel, long woff,
               const float* __restrict__ bias, int K)
{
    extern __shared__ __align__(16) char dynsm[];
    __nv_bfloat16* As = (__nv_bfloat16*)dynsm;
    __nv_bfloat16* Bs = As + GSTAGES * A2_BUF;

    const __nv_bfloat16* A = (asel == 0) ? g_Ain : g_h[asel - 1];
    const __nv_bfloat16* W = ((wsel == 0) ? g_Win : g_Wh) + woff;
    __nv_bfloat16* C = g_h[csel];
    const int N = HID;

    const int bm0 = blockIdx.x * 128;
    const int bn0 = blockIdx.y * 128;
    const int tid  = threadIdx.x;
    const int lane = tid & 31;
    const int warp = tid >> 5;
    const int wm   = warp & 3;
    const int wn   = warp >> 2;

    const int KT = K >> 6;  // BK = 64

    auto load_tile = [&](int kt, int buf) {
        const __nv_bfloat16* Ag = A + (long)bm0 * K + kt * 64;
        __nv_bfloat16* as = As + buf * A2_BUF;
        #pragma unroll
        for (int it = 0; it < 4; ++it) {
            int c = tid + it * 256;
            int row = c >> 3;          // 8 chunks of 16B per 64-col row
            int co  = (c & 7) * 8;
            cp16(as + row * A2_STRIDE + co, Ag + (long)row * K + co);
        }
        const __nv_bfloat16* Wg = W + (long)(kt * 64) * N + bn0;
        __nv_bfloat16* bs = Bs + buf * B2_BUF;
        #pragma unroll
        for (int it = 0; it < 4; ++it) {
            int c = tid + it * 256;
            int row = c >> 4;          // 16 chunks per 128-col row
            int co  = (c & 15) * 8;
            cp16(bs + row * B2_STRIDE + co, Wg + (long)row * N + co);
        }
    };

    float acc[2][8][4] = {};

    load_tile(0, 0); cp_commit();
    load_tile(1, 1); cp_commit();

    for (int kt = 0; kt < KT; ++kt) {
        cp_wait1();             // stage kt has landed (kt+1 may still be in flight)
        __syncthreads();
        if (kt + 2 < KT) load_tile(kt + 2, (kt + 2) % GSTAGES);
        cp_commit();            // always commit (empty groups keep counting consistent)

        const __nv_bfloat16* as = As + (kt % GSTAGES) * A2_BUF;
        const __nv_bfloat16* bs = Bs + (kt % GSTAGES) * B2_BUF;

        #pragma unroll
        for (int ks = 0; ks < 4; ++ks) {
            unsigned a[2][4], bq[4][4];
            int ar = wm * 32 + (lane & 15);
            int ac = ks * 16 + (lane >> 4) * 8;
            ldmA(a[0], as + ar * A2_STRIDE + ac);
            ldmA(a[1], as + (ar + 16) * A2_STRIDE + ac);
            int br = ks * 16 + (lane & 15);
            #pragma unroll
            for (int nb = 0; nb < 4; ++nb)
                ldmBT(bq[nb], bs + br * B2_STRIDE + wn * 64 + nb * 16 + (lane >> 4) * 8);
            #pragma unroll
            for (int m = 0; m < 2; ++m)
                #pragma unroll
                for (int nb = 0; nb < 4; ++nb) {
                    mma16816(acc[m][nb * 2 + 0], a[m], bq[nb][0], bq[nb][1]);
                    mma16816(acc[m][nb * 2 + 1], a[m], bq[nb][2], bq[nb][3]);
                }
        }
    }

    // epilogue: bias + relu -> bf16
    #pragma unroll
    for (int m = 0; m < 2; ++m)
        #pragma unroll
        for (int nt = 0; nt < 8; ++nt) {
            int gr = bm0 + wm * 32 + m * 16 + (lane >> 2);
            int gc = bn0 + wn * 64 + nt * 8 + (lane & 3) * 2;
            float b0 = bias[gc], b1 = bias[gc + 1];
            float v0 = fmaxf(acc[m][nt][0] + b0, 0.f);
            float v1 = fmaxf(acc[m][nt][1] + b1, 0.f);
            float v2 = fmaxf(acc[m][nt][2] + b0, 0.f);
            float v3 = fmaxf(acc[m][nt][3] + b1, 0.f);
            __nv_bfloat162 p0, p1;
            p0.x = __float2bfloat16(v0); p0.y = __float2bfloat16(v1);
            p1.x = __float2bfloat16(v2); p1.y = __float2bfloat16(v3);
            *reinterpret_cast<__nv_bfloat162*>(C + (long)gr * N + gc) = p0;
            *reinterpret_cast<__nv_bfloat162*>(C + (long)(gr + 8) * N + gc) = p1;
        }
}

// ======================================================================
// Out-GEMM v3: BM=64, N=64, K=512, BK=64, 4-stage cp.async (wait_group 2),
// 256 thr (8 warps 4Mx2N, warp tile 16x32). Deep prefetch hides L2 latency.
// ======================================================================
#define AO_STRIDE 72                       // 64 cols + 8 pad (144B rows)
#define AO_BUF (64 * AO_STRIDE)            // per-stage A (elems)
#define OSTAGES 4
#define OSTAGE_ELEMS (2 * AO_BUF)          // A then B per stage
#define GEMMOUT_SMEM (OSTAGES * OSTAGE_ELEMS * 2)  // 73728 bytes
#define PS2_STRIDE 65

__global__ void __launch_bounds__(256)
gemm_out_kernel(int hsel, long woff, const float* __restrict__ bias,
                int layer, const int* __restrict__ perm, float* __restrict__ d_out)
{
    extern __shared__ __align__(16) char dynsm[];
    __shared__ int sperm[64];
    __nv_bfloat16* Sg = (__nv_bfloat16*)dynsm;  // staging; ps overlays later
    float* ps = (float*)dynsm;

    if (perm && threadIdx.x < 64) sperm[threadIdx.x] = perm[threadIdx.x];

    const __nv_bfloat16* A = g_h[hsel];
    const __nv_bfloat16* W = g_Wout + woff;   // [512 x 64]
    const int bm0 = blockIdx.x * 64;
    const int tid  = threadIdx.x;
    const int lane = tid & 31;
    const int warp = tid >> 5;
    const int wm   = warp & 3;                // M: 4 x 16 rows
    const int wn   = warp >> 2;               // N: 2 x 32 cols
    const int KT   = HID >> 6;                // 8 iters of BK=64

    auto load_tile = [&](int kt, int stage) {
        __nv_bfloat16* as = Sg + stage * OSTAGE_ELEMS;
        __nv_bfloat16* bs = as + AO_BUF;
        const __nv_bfloat16* Ag = A + (long)bm0 * HID + kt * 64;
        const __nv_bfloat16* Wg = W + (long)(kt * 64) * FDIM;
        #pragma unroll
        for (int it = 0; it < 2; ++it) {
            int c = tid + it * 256;
            int row = c >> 3;
            int co  = (c & 7) * 8;
            cp16(as + row * AO_STRIDE + co, Ag + (long)row * HID + co);
            cp16(bs + row * AO_STRIDE + co, Wg + (long)row * FDIM + co);
        }
    };

    float acc[4][4] = {};

    load_tile(0, 0); cp_commit();
    load_tile(1, 1); cp_commit();
    load_tile(2, 2); cp_commit();

    for (int kt = 0; kt < KT; ++kt) {
        cp_wait2();            // tile kt landed; kt+1, kt+2 may be in flight
        __syncthreads();
        if (kt + 3 < KT) load_tile(kt + 3, (kt + 3) % OSTAGES);
        cp_commit();           // always commit to keep group counting consistent

        const __nv_bfloat16* as = Sg + (kt % OSTAGES) * OSTAGE_ELEMS;
        const __nv_bfloat16* bs = as + AO_BUF;

        #pragma unroll
        for (int ks = 0; ks < 4; ++ks) {
            unsigned a[4], bq[2][4];
            int ar = wm * 16 + (lane & 15);
            int ac = ks * 16 + (lane >> 4) * 8;
            ldmA(a, as + ar * AO_STRIDE + ac);
            int br = ks * 16 + (lane & 15);
            #pragma unroll
            for (int nb = 0; nb < 2; ++nb)
                ldmBT(bq[nb], bs + br * AO_STRIDE + wn * 32 + nb * 16 + (lane >> 4) * 8);
            #pragma unroll
            for (int nb = 0; nb < 2; ++nb) {
                mma16816(acc[nb * 2 + 0], a, bq[nb][0], bq[nb][1]);
                mma16816(acc[nb * 2 + 1], a, bq[nb][2], bq[nb][3]);
            }
        }
    }
    __syncthreads();   // everyone done with staging before ps overwrites it

    #pragma unroll
    for (int nt = 0; nt < 4; ++nt) {
        int r = wm * 16 + (lane >> 2);
        int c = wn * 32 + nt * 8 + (lane & 3) * 2;
        float b0 = bias[c], b1 = bias[c + 1];
        ps[r * PS2_STRIDE + c]           = acc[nt][0] + b0;
        ps[r * PS2_STRIDE + c + 1]       = acc[nt][1] + b1;
        ps[(r + 8) * PS2_STRIDE + c]     = acc[nt][2] + b0;
        ps[(r + 8) * PS2_STRIDE + c + 1] = acc[nt][3] + b1;
    }
    __syncthreads();

    if (threadIdx.x < 64) {
        int  r  = threadIdx.x;
        long gr = bm0 + r;
        const float* xc = g_x[layer & 1] + gr * FDIM;
        float* prow = ps + r * PS2_STRIDE;
        const int toff = layer & 1;

        float scale[32], shift[32];
        float ld = 0.f;
        #pragma unroll
        for (int k = 0; k < 32; ++k) {
            shift[k] = prow[k];
            float s  = prow[32 + k];
            scale[k] = 1.f / (1.f + expf(-(s + 2.f))) + 0.001f;
            ld += logf(scale[k]);
        }
        #pragma unroll
        for (int k = 0; k < 32; ++k) {
            int t  = 2 * k + toff;
            int id = 2 * k + 1 - toff;
            float xt = xc[t] * scale[k] + shift[k];
            float xi = xc[id];
            prow[t]  = xt;
            prow[id] = xi;
        }

        if (perm) {
            g_logdet[gr] += ld;
            float* xn = g_x[(layer & 1) ^ 1] + gr * FDIM;
            const int idoff = layer & 1;
            #pragma unroll
            for (int j = 0; j < 64; ++j) xn[j] = prow[sperm[j]];
            #pragma unroll
            for (int k = 0; k < 32; ++k)
                g_Ain[gr * KINP + k] = __float2bfloat16(prow[sperm[2 * k + idoff]]);
        } else {
            float tot = g_logdet[gr] + ld;
            #pragma unroll
            for (int j = 0; j < 64; ++j) {
                float v = prow[j];
                v = fminf(fmaxf(v, -1.f), 1.f);
                d_out[gr * FDIM + j] = v;
            }
            d_out[(long)BATCH * FDIM + gr] = tot;
        }
    }
}

// ---------------- init: x0 = clip(inputs), build A_in(layer0), zero logdet ----------------
__global__ void init_kernel(const float* __restrict__ inputs,
                            const float* __restrict__ context)
{
    int r = blockIdx.x * 4 + threadIdx.y;
    int c = threadIdx.x;  // 0..63
    __shared__ float xs[4][64];

    float v = inputs[(long)r * FDIM + c];
    v = fminf(fmaxf(v, -1.f), 1.f);
    g_x[0][(long)r * FDIM + c] = v;
    xs[threadIdx.y][c] = v;

    g_Ain[(long)r * KINP + 32 + c]      = __float2bfloat16(context[(long)r * CTXD + c]);
    g_Ain[(long)r * KINP + 32 + 64 + c] = __float2bfloat16(context[(long)r * CTXD + 64 + c]);
    if (c < 32)  // K padding (cols 160..191) stays zero
        g_Ain[(long)r * KINP + KIN + c] = __float2bfloat16(0.f);
    __syncthreads();
    if (c < 32)  // layer 0: identity = odd columns
        g_Ain[(long)r * KINP + c] = __float2bfloat16(xs[threadIdx.y][2 * c + 1]);
    if (c == 0) g_logdet[r] = 0.f;
}

// ---------------- weight fp32 -> bf16 (W_in K-padded to 192) ----------------
__global__ void cvt_kernel(const float* __restrict__ win,
                           const float* __restrict__ wh,
                           const float* __restrict__ wout)
{
    const long n1 = (long)NLAYERS * KINP * HID;
    const long n2 = (long)NLAYERS * NBLK * HID * HID;
    const long n3 = (long)NLAYERS * HID * FDIM;
    const long total = n1 + n2 + n3;
    for (long i = (long)blockIdx.x * blockDim.x + threadIdx.x; i < total;
         i += (long)gridDim.x * blockDim.x) {
        if (i < n1) {
            long l = i / ((long)KINP * HID);
            long r = (i / HID) % KINP;
            long c = i % HID;
            g_Win[i] = (r < KIN) ? __float2bfloat16(win[(l * KIN + r) * HID + c])
                                 : __float2bfloat16(0.f);
        } else if (i < n1 + n2) {
            g_Wh[i - n1] = __float2bfloat16(wh[i - n1]);
        } else {
            g_Wout[i - n1 - n2] = __float2bfloat16(wout[i - n1 - n2]);
        }
    }
}

// ---------------- launch ----------------
extern "C" void kernel_launch(void* const* d_in, const int* in_sizes, int n_in,
                              void* d_out, int out_size)
{
    const float* inputs  = (const float*)d_in[0];
    const float* context = (const float*)d_in[1];
    const float* W_in    = (const float*)d_in[2];
    const float* b_in    = (const float*)d_in[3];
    const float* W_h     = (const float*)d_in[4];
    const float* b_h     = (const float*)d_in[5];
    const float* W_out   = (const float*)d_in[6];
    const float* b_out   = (const float*)d_in[7];
    const int*   perms   = (const int*)d_in[8];
    float* out = (float*)d_out;

    cudaFuncSetAttribute(gemm128_kernel,
                         cudaFuncAttributeMaxDynamicSharedMemorySize, GEMM128_SMEM);
    cudaFuncSetAttribute(gemm_out_kernel,
                         cudaFuncAttributeMaxDynamicSharedMemorySize, GEMMOUT_SMEM);

    cvt_kernel<<<2048, 256>>>(W_in, W_h, W_out);
    init_kernel<<<BATCH / 4, dim3(64, 4)>>>(inputs, context);

    dim3 gg(BATCH / 128, HID / 128);
    for (int i = 0; i < NLAYERS; ++i) {
        // h0 = relu([id, ctx, pad] @ W_in[i] + b_in[i]), K = 192
        gemm128_kernel<<<gg, 256, GEMM128_SMEM>>>(
            0, 0, 0, (long)i * KINP * HID, b_in + i * HID, KINP);
        // h1 = relu(h0 @ W_h[i,0] + b)
        gemm128_kernel<<<gg, 256, GEMM128_SMEM>>>(
            1, 1, 1, (long)(i * NBLK + 0) * HID * HID, b_h + (i * NBLK + 0) * HID, HID);
        // h0 = relu(h1 @ W_h[i,1] + b)
        gemm128_kernel<<<gg, 256, GEMM128_SMEM>>>(
            2, 0, 1, (long)(i * NBLK + 1) * HID * HID, b_h + (i * NBLK + 1) * HID, HID);
        // p = h0 @ W_out[i] + b_out[i]; flow epilogue + permutation (+final output)
        const int* p = (i < NLAYERS - 1) ? (perms + i * FDIM) : (const int*)nullptr;
        gemm_out_kernel<<<BATCH / 64, 256, GEMMOUT_SMEM>>>(
            0, (long)i * HID * FDIM, b_out + i * FDIM, i, p, out);
    }
}